// round 9
// baseline (speedup 1.0000x reference)
#include <cuda_runtime.h>
#include <math.h>

// Problem constants: B=2, N=4096, D=256, H=64, K=16
#define OUT_ATTN_OFF 2097152  // 2*4096*256

// ---------------- device scratch (no cudaMalloc allowed) ----------------
__device__ float d_Wstack[768 * 256];   // rows 0-255: W_alpha ; 256-511: A=Wg1*Wphi ; 512-767: Bm=Wg1*Wpsi
__device__ float d_Wg2T[256 * 256];     // Wg2T[i][d] = W_g2[d][i]
__device__ float d_Wp2T[64 * 256];      // Wp2T[h][d] = W_p2[d][h]
__device__ float d_CT[64 * 256];        // CT[h][d]   = (Wg1*Wp2)[d][h]
__device__ float d_biash[256];          // b_g1 + Wg1*(b_p2 + b_phi - b_psi)
__device__ float d_nodebuf[8192 * 768]; // per node: [v(256) | qg(256) | kg(256)]
__device__ float d_pos[8192 * 16 * 256];// pos_enc+b_p2 per (point, j, channel)
__device__ int   d_knn[8192 * 16];

// ---------------- packed f32x2 helpers (Blackwell FFMA2) ----------------
__device__ __forceinline__ unsigned long long pack2(float x, float y) {
    unsigned long long r;
    asm("mov.b64 %0, {%1, %2};" : "=l"(r) : "f"(x), "f"(y));
    return r;
}
__device__ __forceinline__ void fma2(unsigned long long& d, unsigned long long a, unsigned long long b) {
    asm("fma.rn.f32x2 %0, %1, %2, %0;" : "+l"(d) : "l"(a), "l"(b));
}
__device__ __forceinline__ float2 unpack2(unsigned long long v) {
    float2 f;
    asm("mov.b64 {%0, %1}, %2;" : "=f"(f.x), "=f"(f.y) : "l"(v));
    return f;
}

// ---------------- fused weight folding (one launch) ----------------
__global__ void k_fold_all(const float* __restrict__ Wg1,
                           const float* __restrict__ Wphi,
                           const float* __restrict__ Wpsi,
                           const float* __restrict__ Walpha,
                           const float* __restrict__ Wg2,
                           const float* __restrict__ Wp2,
                           const float* __restrict__ bg1,
                           const float* __restrict__ bphi,
                           const float* __restrict__ bpsi,
                           const float* __restrict__ bp2) {
    __shared__ float row[256];
    int blk = blockIdx.x, t = threadIdx.x;
    if (blk < 512) {
        int r = blk;
        int src = (r < 256) ? r : r - 256;
        row[t] = Wg1[src * 256 + t];
        __syncthreads();
        const float* W = (r < 256) ? Wphi : Wpsi;
        float acc = 0.f;
        for (int i = 0; i < 256; i++) acc += row[i] * W[i * 256 + t];
        d_Wstack[(256 + r) * 256 + t] = acc;
    } else if (blk < 1088) {
        int r = blk - 512;   // 0..575
        if (r < 256) {
            d_Wstack[r * 256 + t] = Walpha[r * 256 + t];
        } else if (r < 512) {
            int dd = r - 256;
            d_Wg2T[t * 256 + dd] = Wg2[dd * 256 + t];
        } else {
            int idx = (r - 512) * 256 + t;
            int dd = idx >> 6, h = idx & 63;
            d_Wp2T[h * 256 + dd] = Wp2[idx];
        }
    } else if (blk < 1344) {
        int o = blk - 1088;
        for (int i = t; i < 256; i += 256) row[i] = Wg1[o * 256 + i];
        __syncthreads();
        if (t < 64) {
            int hh = t;
            float acc = 0.f;
            for (int tt = 0; tt < 256; tt++) acc += row[tt] * Wp2[tt * 64 + hh];
            d_CT[hh * 256 + o] = acc;
        }
    } else {
        row[t] = bp2[t] + bphi[t] - bpsi[t];
        __syncthreads();
        int wid = t >> 5, lane = t & 31;
        int o = (blk - 1344) * 8 + wid;
        float acc = 0.f;
#pragma unroll
        for (int i = lane; i < 256; i += 32) acc += Wg1[o * 256 + i] * row[i];
#pragma unroll
        for (int off = 16; off > 0; off >>= 1) acc += __shfl_down_sync(0xffffffff, acc, off);
        if (lane == 0) d_biash[o] = bg1[o] + acc;
    }
}

// ---------------- KNN v3: 8 threads per query, merged top-16 ----------------
__global__ void __launch_bounds__(256) knn_kernel(const float* __restrict__ xyz) {
    __shared__ float pool[8320];
    float* tx  = pool;          // [8][260]
    float* tyy = pool + 2080;
    float* tz  = pool + 4160;
    float* tsq = pool + 6240;
    float* md  = pool;                    // [32][129] reused after tiles done
    int*   mi  = (int*)(pool + 4160);     // [32][129]

    int tid = threadIdx.x;
    int q = tid >> 3, part = tid & 7;
    int gq = blockIdx.x * 32 + q;        // 256 blocks * 32 = 8192 queries
    int b = gq >> 12;
    float qx = xyz[gq * 3 + 0], qy = xyz[gq * 3 + 1], qz = xyz[gq * 3 + 2];
    float sqq = qx * qx + qy * qy + qz * qz;
    float bd[16];
    int   bi[16];
#pragma unroll
    for (int j = 0; j < 16; j++) { bd[j] = 3.4e38f; bi[j] = 0x7fffffff; }

    for (int t4 = 0; t4 < 2; t4++) {
        __syncthreads();
#pragma unroll
        for (int r = 0; r < 8; r++) {
            int e = r * 256 + tid;       // 0..2047
            int pp = e >> 8, s = e & 255;
            int g = (b << 12) + (2 * pp + t4) * 256 + s;
            float x = xyz[g * 3 + 0], y = xyz[g * 3 + 1], z = xyz[g * 3 + 2];
            tx[pp * 260 + s] = x; tyy[pp * 260 + s] = y; tz[pp * 260 + s] = z;
            tsq[pp * 260 + s] = x * x + y * y + z * z;
        }
        __syncthreads();
        int mbase = (2 * part + t4) * 256;
        int pb = part * 260;
#pragma unroll 2
        for (int s = 0; s < 256; s++) {
            float dot = qx * tx[pb + s] + qy * tyy[pb + s] + qz * tz[pb + s];
            float d2 = sqq + tsq[pb + s] - 2.f * dot;
            int m = mbase + s;
            if (d2 < bd[15] || (d2 == bd[15] && m < bi[15])) {
                bd[15] = d2; bi[15] = m;
#pragma unroll
                for (int u = 15; u >= 1; --u) {
                    bool sw = bd[u] < bd[u - 1] || (bd[u] == bd[u - 1] && bi[u] < bi[u - 1]);
                    if (sw) {
                        float td = bd[u]; bd[u] = bd[u - 1]; bd[u - 1] = td;
                        int ti = bi[u];  bi[u] = bi[u - 1];  bi[u - 1] = ti;
                    }
                }
            }
        }
    }
    __syncthreads();
#pragma unroll
    for (int j = 0; j < 16; j++) {
        md[q * 129 + part * 16 + j] = bd[j];
        mi[q * 129 + part * 16 + j] = bi[j];
    }
    __syncthreads();
    if (part == 0) {
        int p[8] = {0, 16, 32, 48, 64, 80, 96, 112};
#pragma unroll
        for (int r = 0; r < 16; r++) {
            float best = 3.5e38f; int bidx = 0x7fffffff; int bl = 0;
#pragma unroll
            for (int l = 0; l < 8; l++) {
                int h = p[l];
                bool valid = h < (l * 16 + 16);
                float dv = valid ? md[q * 129 + h] : 3.5e38f;
                int   iv = valid ? mi[q * 129 + h] : 0x7fffffff;
                if (dv < best || (dv == best && iv < bidx)) { best = dv; bidx = iv; bl = l; }
            }
            p[bl]++;
            d_knn[gq * 16 + r] = bidx;
        }
    }
}

// ---------------- per-node GEMM: nodebuf = feat @ Wstack^T (+bias on v block) ----------------
__global__ void node_gemm(const float* __restrict__ feat,
                          const float* __restrict__ balpha) {
    __shared__ float As[16][68];
    __shared__ float Bs[16][68];
    int tx = threadIdx.x, ty = threadIdx.y;
    int t = ty * 16 + tx;
    int o0 = blockIdx.x * 64, m0 = blockIdx.y * 64;
    unsigned long long acc2[4][2];
#pragma unroll
    for (int i = 0; i < 4; i++) { acc2[i][0] = 0ull; acc2[i][1] = 0ull; }
    int lm = t >> 2, lk = (t & 3) * 4;
    for (int k0 = 0; k0 < 256; k0 += 16) {
        float4 fa = *(const float4*)&feat[(m0 + lm) * 256 + k0 + lk];
        float4 fb = *(const float4*)&d_Wstack[(o0 + lm) * 256 + k0 + lk];
        __syncthreads();
        As[lk + 0][lm] = fa.x; As[lk + 1][lm] = fa.y; As[lk + 2][lm] = fa.z; As[lk + 3][lm] = fa.w;
        Bs[lk + 0][lm] = fb.x; Bs[lk + 1][lm] = fb.y; Bs[lk + 2][lm] = fb.z; Bs[lk + 3][lm] = fb.w;
        __syncthreads();
#pragma unroll
        for (int kk = 0; kk < 16; kk++) {
            float4 a = *(const float4*)&As[kk][ty * 4];
            const unsigned long long* bp = (const unsigned long long*)&Bs[kk][tx * 4];
            unsigned long long b01 = bp[0], b23 = bp[1];
            unsigned long long ax = pack2(a.x, a.x), ay = pack2(a.y, a.y);
            unsigned long long az = pack2(a.z, a.z), aw = pack2(a.w, a.w);
            fma2(acc2[0][0], ax, b01); fma2(acc2[0][1], ax, b23);
            fma2(acc2[1][0], ay, b01); fma2(acc2[1][1], ay, b23);
            fma2(acc2[2][0], az, b01); fma2(acc2[2][1], az, b23);
            fma2(acc2[3][0], aw, b01); fma2(acc2[3][1], aw, b23);
        }
    }
#pragma unroll
    for (int i = 0; i < 4; i++) {
        int m = m0 + ty * 4 + i;
        float2 p0 = unpack2(acc2[i][0]);
        float2 p1 = unpack2(acc2[i][1]);
        float vals[4] = { p0.x, p0.y, p1.x, p1.y };
#pragma unroll
        for (int j = 0; j < 4; j++) {
            int o = o0 + tx * 4 + j;
            float bias = (o < 256) ? balpha[o] : 0.f;
            d_nodebuf[m * 768 + o] = vals[j] + bias;
        }
    }
}

// ---------------- phase C pass: 4 contiguous channels (cq..cq+3) x 4 j ----------------
__device__ __forceinline__ void phaseC_pass(
    int cq, int ph, int q, int g,
    const float* pe1s, float* h1s, const int* gmj,
    const float* __restrict__ bp2) {
    unsigned long long pos[2][4], cc[2][4];
#pragma unroll
    for (int cp = 0; cp < 2; cp++)
#pragma unroll
        for (int j = 0; j < 4; j++) { pos[cp][j] = 0ull; cc[cp][j] = 0ull; }
#pragma unroll 2
    for (int hh = 0; hh < 64; hh++) {
        ulonglong2 w2 = *(const ulonglong2*)&d_Wp2T[hh * 256 + cq];
        ulonglong2 wc = *(const ulonglong2*)&d_CT[hh * 256 + cq];
        float4 pv = *(const float4*)&pe1s[hh * 36 + ph * 16 + q * 4];
        unsigned long long h0 = pack2(pv.x, pv.x), h1 = pack2(pv.y, pv.y);
        unsigned long long h2 = pack2(pv.z, pv.z), h3 = pack2(pv.w, pv.w);
        fma2(pos[0][0], w2.x, h0); fma2(pos[0][1], w2.x, h1);
        fma2(pos[0][2], w2.x, h2); fma2(pos[0][3], w2.x, h3);
        fma2(pos[1][0], w2.y, h0); fma2(pos[1][1], w2.y, h1);
        fma2(pos[1][2], w2.y, h2); fma2(pos[1][3], w2.y, h3);
        fma2(cc[0][0], wc.x, h0); fma2(cc[0][1], wc.x, h1);
        fma2(cc[0][2], wc.x, h2); fma2(cc[0][3], wc.x, h3);
        fma2(cc[1][0], wc.y, h0); fma2(cc[1][1], wc.y, h1);
        fma2(cc[1][2], wc.y, h2); fma2(cc[1][3], wc.y, h3);
    }
    float4 qgq = *(const float4*)&d_nodebuf[g * 768 + 256 + cq];
    float4 bhq = *(const float4*)&d_biash[cq];
    float4 bpq = *(const float4*)&bp2[cq];
    float posf[4][4], ccf[4][4];
#pragma unroll
    for (int j = 0; j < 4; j++) {
        float2 p0 = unpack2(pos[0][j]);
        float2 p1 = unpack2(pos[1][j]);
        posf[0][j] = p0.x + bpq.x; posf[1][j] = p0.y + bpq.y;
        posf[2][j] = p1.x + bpq.z; posf[3][j] = p1.y + bpq.w;
        float2 c0 = unpack2(cc[0][j]);
        float2 c1 = unpack2(cc[1][j]);
        ccf[0][j] = c0.x; ccf[1][j] = c0.y; ccf[2][j] = c1.x; ccf[3][j] = c1.y;
    }
    float h1o[4][4];
#pragma unroll
    for (int j = 0; j < 4; j++) {
        int jg = q * 4 + j;
        int gm = gmj[j];
        float4 kg = *(const float4*)&d_nodebuf[gm * 768 + 512 + cq];
        h1o[0][j] = fmaxf(ccf[0][j] + qgq.x - kg.x + bhq.x, 0.f);
        h1o[1][j] = fmaxf(ccf[1][j] + qgq.y - kg.y + bhq.y, 0.f);
        h1o[2][j] = fmaxf(ccf[2][j] + qgq.z - kg.z + bhq.z, 0.f);
        h1o[3][j] = fmaxf(ccf[3][j] + qgq.w - kg.w + bhq.w, 0.f);
        *(float4*)&d_pos[(g * 16 + jg) * 256 + cq] =
            make_float4(posf[0][j], posf[1][j], posf[2][j], posf[3][j]);
    }
#pragma unroll
    for (int ch = 0; ch < 4; ch++)
        *(float4*)&h1s[(cq + ch) * 36 + ph * 16 + q * 4] =
            make_float4(h1o[ch][0], h1o[ch][1], h1o[ch][2], h1o[ch][3]);
}

// ---------------- main fused attention: warp = 64ch x 16j of one point ----------------
// Block: 8 warps, 2 points. Warp w: ph=w>>2, chb=(w&3)*64. Lane l: o=l>>2, q=l&3.
// Thread: channels {chb+o*4..+3, chb+32+o*4..+3}, j's {q*4..q*4+3}.
__global__ void __launch_bounds__(256, 3) pt_main_kernel(
    const float* __restrict__ xyz,
    const float* __restrict__ Wp1, const float* __restrict__ bp1,
    const float* __restrict__ bp2, const float* __restrict__ bg2,
    float* __restrict__ out) {
    __shared__ __align__(16) float pe1s[64 * 36];   // [h][jp], jp = p*16+j
    __shared__ __align__(16) float h1s[256 * 36];   // [i][jp]
    __shared__ float nx[32], ny[32], nz[32];
    __shared__ int idxs[32];
    __shared__ float q3[2][3];

    int g0 = blockIdx.x * 2;
    int b = g0 >> 12;
    int tid = threadIdx.x;
    int w = tid >> 5, lane = tid & 31;
    int ph = w >> 2;
    int chb = (w & 3) * 64;
    int o = lane >> 2, q = lane & 3;
    int cqA = chb + o * 4, cqB = chb + 32 + o * 4;
    int g = g0 + ph;

    if (tid < 32) idxs[tid] = d_knn[g0 * 16 + tid];
    if (tid < 6)  q3[tid / 3][tid % 3] = xyz[(g0 + tid / 3) * 3 + (tid % 3)];
    __syncthreads();
    if (tid < 96) {
        int jp = tid / 3, c = tid % 3;
        float v = xyz[((b << 12) + idxs[jp]) * 3 + c];
        if (c == 0) nx[jp] = v; else if (c == 1) ny[jp] = v; else nz[jp] = v;
    }
    int gmj[4];
#pragma unroll
    for (int j = 0; j < 4; j++) gmj[j] = (b << 12) + idxs[ph * 16 + q * 4 + j];
    __syncthreads();

    // phase B: pe1[jp][h] = relu(W_p1 rel + b_p1)
#pragma unroll
    for (int r = 0; r < 8; r++) {
        int idx = r * 256 + tid;
        int jp = idx & 31, hh = idx >> 5;
        int p = jp >> 4;
        float rx = q3[p][0] - nx[jp], ry = q3[p][1] - ny[jp], rz = q3[p][2] - nz[jp];
        float v = bp1[hh] + Wp1[hh * 3 + 0] * rx + Wp1[hh * 3 + 1] * ry + Wp1[hh * 3 + 2] * rz;
        pe1s[hh * 36 + jp] = fmaxf(v, 0.f);
    }
    __syncthreads();

    // phase C: two channel-quad passes
    phaseC_pass(cqA, ph, q, g, pe1s, h1s, gmj, bp2);
    phaseC_pass(cqB, ph, q, g, pe1s, h1s, gmj, bp2);
    __syncthreads();

    // phase D: attn[c][j] = sum_i Wg2T[i][c] * h1[i][j]
    unsigned long long acc[4][4];   // chpair (cqA+0/1, cqA+2/3, cqB+0/1, cqB+2/3) x j
#pragma unroll
    for (int cp = 0; cp < 4; cp++)
#pragma unroll
        for (int j = 0; j < 4; j++) acc[cp][j] = 0ull;
#pragma unroll 2
    for (int i = 0; i < 256; i++) {
        ulonglong2 wA = *(const ulonglong2*)&d_Wg2T[i * 256 + cqA];
        ulonglong2 wB = *(const ulonglong2*)&d_Wg2T[i * 256 + cqB];
        float4 hv = *(const float4*)&h1s[i * 36 + ph * 16 + q * 4];
        unsigned long long h0 = pack2(hv.x, hv.x), h1 = pack2(hv.y, hv.y);
        unsigned long long h2 = pack2(hv.z, hv.z), h3 = pack2(hv.w, hv.w);
        fma2(acc[0][0], wA.x, h0); fma2(acc[0][1], wA.x, h1);
        fma2(acc[0][2], wA.x, h2); fma2(acc[0][3], wA.x, h3);
        fma2(acc[1][0], wA.y, h0); fma2(acc[1][1], wA.y, h1);
        fma2(acc[1][2], wA.y, h2); fma2(acc[1][3], wA.y, h3);
        fma2(acc[2][0], wB.x, h0); fma2(acc[2][1], wB.x, h1);
        fma2(acc[2][2], wB.x, h2); fma2(acc[2][3], wB.x, h3);
        fma2(acc[3][0], wB.y, h0); fma2(acc[3][1], wB.y, h1);
        fma2(acc[3][2], wB.y, h2); fma2(acc[3][3], wB.y, h3);
    }

    // epilogue: bias + scale + 16-way softmax (4 local j x 4 lanes in q-group)
    float af[8][4];
#pragma unroll
    for (int cp = 0; cp < 4; cp++)
#pragma unroll
        for (int j = 0; j < 4; j++) {
            float2 v = unpack2(acc[cp][j]);
            af[2 * cp][j] = v.x; af[2 * cp + 1][j] = v.y;
        }
    float4 bgA = *(const float4*)&bg2[cqA];
    float4 bgB = *(const float4*)&bg2[cqB];
    float bgv[8] = { bgA.x, bgA.y, bgA.z, bgA.w, bgB.x, bgB.y, bgB.z, bgB.w };
#pragma unroll
    for (int ch = 0; ch < 8; ch++) {
#pragma unroll
        for (int j = 0; j < 4; j++) af[ch][j] = (af[ch][j] + bgv[ch]) * 0.0625f;
        float m = fmaxf(fmaxf(af[ch][0], af[ch][1]), fmaxf(af[ch][2], af[ch][3]));
        m = fmaxf(m, __shfl_xor_sync(0xffffffff, m, 1));
        m = fmaxf(m, __shfl_xor_sync(0xffffffff, m, 2));
        float s = 0.f;
#pragma unroll
        for (int j = 0; j < 4; j++) { af[ch][j] = expf(af[ch][j] - m); s += af[ch][j]; }
        s += __shfl_xor_sync(0xffffffff, s, 1);
        s += __shfl_xor_sync(0xffffffff, s, 2);
        float inv = 1.f / s;
#pragma unroll
        for (int j = 0; j < 4; j++) af[ch][j] *= inv;
    }

    // store attn weights + weighted sum of (v + pos)
    float facc[8];
#pragma unroll
    for (int ch = 0; ch < 8; ch++) facc[ch] = 0.f;
#pragma unroll
    for (int j = 0; j < 4; j++) {
        int jg = q * 4 + j;
        int gm = gmj[j];
        int obase = OUT_ATTN_OFF + (g * 16 + jg) * 256;
        *(float4*)&out[obase + cqA] = make_float4(af[0][j], af[1][j], af[2][j], af[3][j]);
        *(float4*)&out[obase + cqB] = make_float4(af[4][j], af[5][j], af[6][j], af[7][j]);
        float4 vA = *(const float4*)&d_nodebuf[gm * 768 + cqA];
        float4 vB = *(const float4*)&d_nodebuf[gm * 768 + cqB];
        float4 pA = *(const float4*)&d_pos[(g * 16 + jg) * 256 + cqA];
        float4 pB = *(const float4*)&d_pos[(g * 16 + jg) * 256 + cqB];
        facc[0] += af[0][j] * (vA.x + pA.x);
        facc[1] += af[1][j] * (vA.y + pA.y);
        facc[2] += af[2][j] * (vA.z + pA.z);
        facc[3] += af[3][j] * (vA.w + pA.w);
        facc[4] += af[4][j] * (vB.x + pB.x);
        facc[5] += af[5][j] * (vB.y + pB.y);
        facc[6] += af[6][j] * (vB.z + pB.z);
        facc[7] += af[7][j] * (vB.w + pB.w);
    }
#pragma unroll
    for (int ch = 0; ch < 8; ch++) {
        facc[ch] += __shfl_xor_sync(0xffffffff, facc[ch], 1);
        facc[ch] += __shfl_xor_sync(0xffffffff, facc[ch], 2);
    }
    if (q == 0) {
        *(float4*)&out[g * 256 + cqA] = make_float4(facc[0], facc[1], facc[2], facc[3]);
        *(float4*)&out[g * 256 + cqB] = make_float4(facc[4], facc[5], facc[6], facc[7]);
    }
}

// ---------------- launch ----------------
extern "C" void kernel_launch(void* const* d_in, const int* in_sizes, int n_in,
                              void* d_out, int out_size) {
    const float* feat   = (const float*)d_in[0];
    const float* xyz    = (const float*)d_in[1];
    const float* Wphi   = (const float*)d_in[2];
    const float* bphi   = (const float*)d_in[3];
    const float* Wpsi   = (const float*)d_in[4];
    const float* bpsi   = (const float*)d_in[5];
    const float* Walpha = (const float*)d_in[6];
    const float* balpha = (const float*)d_in[7];
    const float* Wg1    = (const float*)d_in[8];
    const float* bg1    = (const float*)d_in[9];
    const float* Wg2    = (const float*)d_in[10];
    const float* bg2    = (const float*)d_in[11];
    const float* Wp1    = (const float*)d_in[12];
    const float* bp1    = (const float*)d_in[13];
    const float* Wp2    = (const float*)d_in[14];
    const float* bp2    = (const float*)d_in[15];
    float* out = (float*)d_out;

    k_fold_all<<<1376, 256>>>(Wg1, Wphi, Wpsi, Walpha, Wg2, Wp2, bg1, bphi, bpsi, bp2);
    knn_kernel<<<256, 256>>>(xyz);
    node_gemm<<<dim3(12, 128), dim3(16, 16)>>>(feat, balpha);
    pt_main_kernel<<<4096, 256>>>(xyz, Wp1, bp1, bp2, bg2, out);
}